// round 5
// baseline (speedup 1.0000x reference)
#include <cuda_runtime.h>
#include <cuda_bf16.h>
#include <math.h>
#include <stdint.h>

#define BB 2
#define NNODES 4096
#define DIMF 128
#define MDIM 16
#define KNN 32
#define HID 530
#define EPAD 544                    // padded hidden (17*32)
#define NODES (BB*NNODES)           // 8192
#define NODE_OUT_ELEMS (NODES*DIMF)
#define NODES_PER_BLK 8

typedef unsigned long long ull;

// ---------------- scratch (static device arrays; no allocation) -------------
__device__ float g_A[NODES * EPAD];    // feats@We1[0:128]+be1 (pad cols zero)
__device__ float g_B[NODES * EPAD];    // feats@We1[128:256]   (pad cols zero)
__device__ float g_XC[NODES * 144];    // [feats | m_i]
__device__ float g_H1[NODES * 256];    // node hidden
__device__ int   g_knn[NODES * KNN];

// ---------------- f32x2 helpers (Blackwell packed fp32) ---------------------
__device__ __forceinline__ ull pack2(float lo, float hi) {
    ull u; asm("mov.b64 %0, {%1, %2};" : "=l"(u) : "f"(lo), "f"(hi)); return u;
}
__device__ __forceinline__ float2 unpack2(ull u) {
    float2 v; asm("mov.b64 {%0, %1}, %2;" : "=f"(v.x), "=f"(v.y) : "l"(u)); return v;
}
__device__ __forceinline__ void ffma2(ull& d, ull a, ull b) {
    asm("fma.rn.f32x2 %0, %1, %2, %0;" : "+l"(d) : "l"(a), "l"(b));
}
__device__ __forceinline__ ull fadd2(ull a, ull b) {
    ull d; asm("add.rn.f32x2 %0, %1, %2;" : "=l"(d) : "l"(a), "l"(b)); return d;
}

__device__ __forceinline__ float silu_f(float x) {
    float e = __expf(-x);
    return __fdividef(x, 1.0f + e);
}

__device__ __forceinline__ float dist2_f(float dx, float dy, float dz) {
    // match reference (no FMA contraction, left-assoc sum)
    return __fadd_rn(__fadd_rn(__fmul_rn(dx, dx), __fmul_rn(dy, dy)), __fmul_rn(dz, dz));
}

// ---------------------------------------------------------------------------
// KNN: one warp per (b,i). Unsorted top-32 set via warp REDUX threshold.
// ---------------------------------------------------------------------------
__global__ __launch_bounds__(256) void knn_kernel(const float* __restrict__ coors) {
    const unsigned FULL = 0xffffffffu;
    int w    = blockIdx.x * 8 + (threadIdx.x >> 5);
    int lane = threadIdx.x & 31;
    int b = w >> 12;
    int i = w & (NNODES - 1);
    const float* cb = coors + (size_t)b * NNODES * 3;
    float qx = cb[3 * i + 0], qy = cb[3 * i + 1], qz = cb[3 * i + 2];

    float dx = qx - cb[3 * lane + 0];
    float dy = qy - cb[3 * lane + 1];
    float dz = qz - cb[3 * lane + 2];
    unsigned bu = __float_as_uint(dist2_f(dx, dy, dz));
    int bj = lane;
    unsigned curmax = __reduce_max_sync(FULL, bu);

    for (int j0 = 32; j0 < NNODES; j0 += 32) {
        int j = j0 + lane;
        float ex = qx - cb[3 * j + 0];
        float ey = qy - cb[3 * j + 1];
        float ez = qz - cb[3 * j + 2];
        unsigned du = __float_as_uint(dist2_f(ex, ey, ez));
        unsigned mask = __ballot_sync(FULL, du < curmax);
        while (mask) {
            int src = __ffs(mask) - 1;
            mask &= mask - 1;
            unsigned dc = __shfl_sync(FULL, du, src);
            if (dc < curmax) {
                unsigned mm = __ballot_sync(FULL, bu == curmax);
                int ml = __ffs(mm) - 1;
                if (lane == ml) { bu = dc; bj = j0 + src; }
                curmax = __reduce_max_sync(FULL, bu);
            }
        }
    }
    g_knn[(size_t)w * KNN + lane] = bj;
}

// ---------------------------------------------------------------------------
// Tiled fp32 GEMM (FFMA2 micro-kernel): C[.. x Npad] = act(X @ W + b) (+resid)
// ---------------------------------------------------------------------------
__global__ __launch_bounds__(256) void gemm_kernel(
    const float* __restrict__ X, int ldx,
    const float* __restrict__ W, int ldw,
    const float* __restrict__ bias,
    const float* __restrict__ resid, int ldr,
    float* __restrict__ C, int ldc,
    int Nw, int Npad, int K, int act)
{
    __shared__ float Xs[16][68];
    __shared__ float Ws[16][68];
    int tid = threadIdx.x;
    int tx = tid & 15, ty = tid >> 4;
    int m0 = blockIdx.y * 64, n0 = blockIdx.x * 64;

    int lm  = tid >> 2;
    int lk  = (tid & 3) * 4;
    int wn  = tid & 63;
    int wkb = (tid >> 6) * 4;

    ull acc2[4][2];
#pragma unroll
    for (int a = 0; a < 4; a++) { acc2[a][0] = 0ull; acc2[a][1] = 0ull; }

    for (int kt = 0; kt < K; kt += 16) {
        float4 xv = *reinterpret_cast<const float4*>(X + (size_t)(m0 + lm) * ldx + kt + lk);
        Xs[lk + 0][lm] = xv.x;
        Xs[lk + 1][lm] = xv.y;
        Xs[lk + 2][lm] = xv.z;
        Xs[lk + 3][lm] = xv.w;
#pragma unroll
        for (int q = 0; q < 4; q++) {
            int k = wkb + q;
            float v = (n0 + wn < Nw) ? W[(size_t)(kt + k) * ldw + n0 + wn] : 0.f;
            Ws[k][wn] = v;
        }
        __syncthreads();
#pragma unroll
        for (int k = 0; k < 16; k++) {
            float4 a4 = *reinterpret_cast<const float4*>(&Xs[k][ty * 4]);
            float4 b4 = *reinterpret_cast<const float4*>(&Ws[k][tx * 4]);
            ull b01 = pack2(b4.x, b4.y);
            ull b23 = pack2(b4.z, b4.w);
            float av[4] = {a4.x, a4.y, a4.z, a4.w};
#pragma unroll
            for (int mi = 0; mi < 4; mi++) {
                ull aa = pack2(av[mi], av[mi]);
                ffma2(acc2[mi][0], aa, b01);
                ffma2(acc2[mi][1], aa, b23);
            }
        }
        __syncthreads();
    }

#pragma unroll
    for (int mi = 0; mi < 4; mi++) {
        int m = m0 + ty * 4 + mi;
        float2 lo = unpack2(acc2[mi][0]);
        float2 hi = unpack2(acc2[mi][1]);
        float accv[4] = {lo.x, lo.y, hi.x, hi.y};
#pragma unroll
        for (int ni = 0; ni < 4; ni++) {
            int n = n0 + tx * 4 + ni;
            if (n < Npad) {
                float v = accv[ni];
                if (n < Nw) {
                    if (bias) v += bias[n];
                    if (act) v = silu_f(v);
                    if (resid) v += resid[(size_t)m * ldr + n];
                } else {
                    v = 0.f;
                }
                C[(size_t)m * ldc + n] = v;
            }
        }
    }
}

// ---------------------------------------------------------------------------
// copy feats into XC[:, 0:128]
// ---------------------------------------------------------------------------
__global__ __launch_bounds__(256) void copy_feats_kernel(const float* __restrict__ feats) {
    int idx = blockIdx.x * 256 + threadIdx.x;  // over NODES*128
    int n = idx >> 7, c = idx & 127;
    g_XC[(size_t)n * 144 + c] = feats[idx];
}

// ---------------------------------------------------------------------------
// Edge kernel: 512 threads, NODES_PER_BLK nodes/block, warp handles 2 edges.
// LDS.128-packed conflict-free weights, FFMA2 math, distance-4 prefetch.
// ---------------------------------------------------------------------------
// float region offsets (after the packed region):
#define SMF_WC1   0                         // [16][64]
#define SMF_BC1   (SMF_WC1 + 1024)          // 64
#define SMF_WC2   (SMF_BC1 + 64)            // 64
#define SMF_BE2   (SMF_WC2 + 64)            // 16
#define SMF_RC    (SMF_BE2 + 16)            // [32][4]
#define SMF_MS    (SMF_RC + 128)            // [32][16]
#define SMF_CW    (SMF_MS + 512)            // 32
#define SMF_JJ    (SMF_CW + 32)             // 32 ints
#define SMF_TOT   (SMF_JJ + 32)
#define EK_SMEM_BYTES ((4*EPAD + 2*EPAD)*16 + (EPAD + 32*6)*8 + SMF_TOT*4)

__global__ __launch_bounds__(512, 1) void edge_kernel(
    const float* __restrict__ coors,
    const float* __restrict__ We1,
    const float* __restrict__ We2,
    const float* __restrict__ be2,
    const float* __restrict__ Wc1,
    const float* __restrict__ bc1,
    const float* __restrict__ Wc2,
    const float* __restrict__ bc2,
    float* __restrict__ coors_out)
{
    extern __shared__ char smraw[];
    ulonglong2* We2P = (ulonglong2*)smraw;        // [4][EPAD] : plane p -> outputs 4p..4p+3
    ulonglong2* FTa  = We2P + 4 * EPAD;           // [2][EPAD] : fourier terms 0-3 / 4-7
    ull* FTb = (ull*)(FTa + 2 * EPAD);            // [EPAD]    : term 8 (paired with 0)
    ull* F2  = FTb + EPAD;                        // [32][6]   : per-edge fourier pairs
    float* smf  = (float*)(F2 + 32 * 6);
    float* Wc1s = smf + SMF_WC1;
    float* bc1s = smf + SMF_BC1;
    float* Wc2s = smf + SMF_WC2;
    float* be2s = smf + SMF_BE2;
    float* rc_s = smf + SMF_RC;
    float* ms   = smf + SMF_MS;
    float* cw_s = smf + SMF_CW;
    int*   jj_s = (int*)(smf + SMF_JJ);

    int tid = threadIdx.x;
    int w = tid >> 5, lane = tid & 31;
    const unsigned FULL = 0xffffffffu;
    float bc2v = bc2[0];

    // ---- load weights once per block (packed, transposed, zero-padded) ----
    for (int idx = tid; idx < 4 * EPAD; idx += 512) {
        int p = idx / EPAD, c = idx - p * EPAD;
        ulonglong2 v; v.x = 0ull; v.y = 0ull;
        if (c < HID) {
            v.x = pack2(We2[c * 16 + 4 * p + 0], We2[c * 16 + 4 * p + 1]);
            v.y = pack2(We2[c * 16 + 4 * p + 2], We2[c * 16 + 4 * p + 3]);
        }
        We2P[idx] = v;
    }
    for (int idx = tid; idx < 2 * EPAD; idx += 512) {
        int t = idx / EPAD, c = idx - t * EPAD;
        ulonglong2 v; v.x = 0ull; v.y = 0ull;
        if (c < HID) {
            v.x = pack2(We1[(size_t)(256 + 4 * t + 0) * HID + c], We1[(size_t)(256 + 4 * t + 1) * HID + c]);
            v.y = pack2(We1[(size_t)(256 + 4 * t + 2) * HID + c], We1[(size_t)(256 + 4 * t + 3) * HID + c]);
        }
        FTa[idx] = v;
    }
    for (int idx = tid; idx < EPAD; idx += 512) {
        ull v = 0ull;
        if (idx < HID) v = pack2(We1[(size_t)264 * HID + idx], 0.f);
        FTb[idx] = v;
    }
    for (int idx = tid; idx < 16 * 64; idx += 512) Wc1s[idx] = Wc1[idx];
    if (tid < 64) { bc1s[tid] = bc1[tid]; Wc2s[tid] = Wc2[tid]; }
    if (tid >= 64 && tid < 80) be2s[tid - 64] = be2[tid - 64];
    __syncthreads();

    for (int nn = 0; nn < NODES_PER_BLK; nn++) {
        int node = blockIdx.x * NODES_PER_BLK + nn;
        int b = node >> 12, i = node & (NNODES - 1);
        const float* cb = coors + (size_t)b * NNODES * 3;

        // ---- per-node setup (warp 0): fourier pairs + rel coords ----
        if (tid < 32) {
            int e = tid;
            int j = g_knn[(size_t)node * KNN + e];
            jj_s[e] = j;
            float dx = cb[3 * i + 0] - cb[3 * j + 0];
            float dy = cb[3 * i + 1] - cb[3 * j + 1];
            float dz = cb[3 * i + 2] - cb[3 * j + 2];
            float d = dist2_f(dx, dy, dz);
            rc_s[e * 4 + 0] = dx; rc_s[e * 4 + 1] = dy; rc_s[e * 4 + 2] = dz; rc_s[e * 4 + 3] = 0.f;
            float s0, c0, s1, c1, s2, c2, s3, c3;
            sincosf(d,          &s0, &c0);
            sincosf(d * 0.5f,   &s1, &c1);
            sincosf(d * 0.25f,  &s2, &c2);
            sincosf(d * 0.125f, &s3, &c3);
            // pairs matching FTa/FTb packing: (t0,t1)=(s0,s1) (t2,t3)=(s2,s3)
            // (t4,t5)=(c0,c1) (t6,t7)=(c2,c3) (t8,-)=(d,0)
            F2[e * 6 + 0] = pack2(s0, s1);
            F2[e * 6 + 1] = pack2(s2, s3);
            F2[e * 6 + 2] = pack2(c0, c1);
            F2[e * 6 + 3] = pack2(c2, c3);
            F2[e * 6 + 4] = pack2(d, 0.f);
        }
        __syncthreads();

        // ---- registerize this warp's 2 edges' fourier pairs ----
        int e0 = w * 2;
        ull fp0[5], fp1[5];
#pragma unroll
        for (int t = 0; t < 5; t++) { fp0[t] = F2[(e0 + 0) * 6 + t]; fp1[t] = F2[(e0 + 1) * 6 + t]; }

        const float* Ap  = g_A + (size_t)node * EPAD;
        const float* Bp0 = g_B + (size_t)(b * NNODES + jj_s[e0 + 0]) * EPAD;
        const float* Bp1 = g_B + (size_t)(b * NNODES + jj_s[e0 + 1]) * EPAD;

        ull m[16];   // [q*8+p]: q = edge (0/1), p = output pair 0..7
#pragma unroll
        for (int q = 0; q < 16; q++) m[q] = 0ull;

        // distance-4 prefetch buffers (covers ~260cyc L2 latency)
        float pav[4], pb0[4], pb1[4];
#pragma unroll
        for (int p = 0; p < 4; p++) {
            pav[p] = Ap[p * 32 + lane];
            pb0[p] = Bp0[p * 32 + lane];
            pb1[p] = Bp1[p * 32 + lane];
        }

#pragma unroll 2
        for (int it = 0; it < 17; it++) {
            int c = it * 32 + lane;
            int buf = it & 3;
            float av = pav[buf], bv0 = pb0[buf], bv1 = pb1[buf];
            if (it + 4 < 17) {
                int c2 = c + 128;
                pav[buf] = Ap[c2]; pb0[buf] = Bp0[c2]; pb1[buf] = Bp1[c2];
            }
            // conflict-free packed weight loads (lanes consecutive in c)
            ulonglong2 fta0 = FTa[c];
            ulonglong2 fta1 = FTa[EPAD + c];
            ull        ftb  = FTb[c];

            // edge0 hidden: two chains, depth 3
            ull h0a = pack2(av + bv0, 0.f);
            ull h0b = 0ull;
            ffma2(h0a, fp0[0], fta0.x);
            ffma2(h0b, fp0[1], fta0.y);
            ffma2(h0a, fp0[2], fta1.x);
            ffma2(h0b, fp0[3], fta1.y);
            ffma2(h0a, fp0[4], ftb);
            float2 h0v = unpack2(fadd2(h0a, h0b));
            float sh0 = silu_f(h0v.x + h0v.y);

            ull h1a = pack2(av + bv1, 0.f);
            ull h1b = 0ull;
            ffma2(h1a, fp1[0], fta0.x);
            ffma2(h1b, fp1[1], fta0.y);
            ffma2(h1a, fp1[2], fta1.x);
            ffma2(h1b, fp1[3], fta1.y);
            ffma2(h1a, fp1[4], ftb);
            float2 h1v = unpack2(fadd2(h1a, h1b));
            float sh1 = silu_f(h1v.x + h1v.y);

            ull sh0p = pack2(sh0, sh0);
            ull sh1p = pack2(sh1, sh1);

            ulonglong2 w0 = We2P[0 * EPAD + c];
            ulonglong2 w1 = We2P[1 * EPAD + c];
            ulonglong2 w2 = We2P[2 * EPAD + c];
            ulonglong2 w3 = We2P[3 * EPAD + c];

            ffma2(m[0], sh0p, w0.x); ffma2(m[1], sh0p, w0.y);
            ffma2(m[2], sh0p, w1.x); ffma2(m[3], sh0p, w1.y);
            ffma2(m[4], sh0p, w2.x); ffma2(m[5], sh0p, w2.y);
            ffma2(m[6], sh0p, w3.x); ffma2(m[7], sh0p, w3.y);

            ffma2(m[8],  sh1p, w0.x); ffma2(m[9],  sh1p, w0.y);
            ffma2(m[10], sh1p, w1.x); ffma2(m[11], sh1p, w1.y);
            ffma2(m[12], sh1p, w2.x); ffma2(m[13], sh1p, w2.y);
            ffma2(m[14], sh1p, w3.x); ffma2(m[15], sh1p, w3.y);
        }

        // ---- reduce-scatter on 16 f32x2 values; final k = lane&15, q = lane>>4
        {
            bool up;
            up = (lane & 16);
#pragma unroll
            for (int v = 0; v < 8; v++) {
                ull give = up ? m[v] : m[v + 8];
                ull recv = __shfl_xor_sync(FULL, give, 16);
                ull keep = up ? m[v + 8] : m[v];
                m[v] = fadd2(keep, recv);
            }
            up = (lane & 8);
#pragma unroll
            for (int v = 0; v < 4; v++) {
                ull give = up ? m[v] : m[v + 4];
                ull recv = __shfl_xor_sync(FULL, give, 8);
                ull keep = up ? m[v + 4] : m[v];
                m[v] = fadd2(keep, recv);
            }
            up = (lane & 4);
#pragma unroll
            for (int v = 0; v < 2; v++) {
                ull give = up ? m[v] : m[v + 2];
                ull recv = __shfl_xor_sync(FULL, give, 4);
                ull keep = up ? m[v + 2] : m[v];
                m[v] = fadd2(keep, recv);
            }
            up = (lane & 2);
            {
                ull give = up ? m[0] : m[1];
                ull recv = __shfl_xor_sync(FULL, give, 2);
                ull keep = up ? m[1] : m[0];
                m[0] = fadd2(keep, recv);
            }
            float2 v2 = unpack2(m[0]);
            bool upc = (lane & 1);
            float give = upc ? v2.x : v2.y;
            float recv = __shfl_xor_sync(FULL, give, 1);
            float tot = (upc ? v2.y : v2.x) + recv;
            int k = lane & 15, q = lane >> 4;
            ms[(e0 + q) * 16 + k] = silu_f(tot + be2s[k]);
        }
        __syncthreads();

        // ---- coors MLP (threads 0-255) and m_i (threads 256-271) ----
        if (tid < 256) {
            int e = tid >> 3, li = tid & 7;
            float wpart = 0.f;
#pragma unroll
            for (int q = 0; q < 8; q++) {
                int l = li * 8 + q;
                float u = bc1s[l];
#pragma unroll
                for (int k = 0; k < 16; k++)
                    u = fmaf(ms[e * 16 + k], Wc1s[k * 64 + l], u);
                wpart = fmaf(silu_f(u), Wc2s[l], wpart);
            }
            wpart += __shfl_xor_sync(FULL, wpart, 1);
            wpart += __shfl_xor_sync(FULL, wpart, 2);
            wpart += __shfl_xor_sync(FULL, wpart, 4);
            if (li == 0) cw_s[e] = wpart + bc2v;
        } else if (tid < 272) {
            int k = tid - 256;
            float s = 0.f;
#pragma unroll 8
            for (int e2 = 0; e2 < 32; e2++) s += ms[e2 * 16 + k];
            g_XC[(size_t)node * 144 + 128 + k] = s;
        }
        __syncthreads();

        // ---- coors_out reduce: warp 0 ----
        if (tid < 32) {
            int e2 = tid;
            float wv = cw_s[e2];
            float px = wv * rc_s[e2 * 4 + 0];
            float py = wv * rc_s[e2 * 4 + 1];
            float pz = wv * rc_s[e2 * 4 + 2];
#pragma unroll
            for (int off = 16; off > 0; off >>= 1) {
                px += __shfl_down_sync(FULL, px, off);
                py += __shfl_down_sync(FULL, py, off);
                pz += __shfl_down_sync(FULL, pz, off);
            }
            if (e2 == 0) {
                float* co = coors_out + (size_t)node * 3;
                co[0] = cb[3 * i + 0] + px;
                co[1] = cb[3 * i + 1] + py;
                co[2] = cb[3 * i + 2] + pz;
            }
        }
        // warp 0's next-node setup writes are program-ordered after its reduce;
        // other warps cross the setup __syncthreads before touching shared.
    }
}

// ---------------------------------------------------------------------------
extern "C" void kernel_launch(void* const* d_in, const int* in_sizes, int n_in,
                              void* d_out, int out_size) {
    const float* feats = (const float*)d_in[0];
    const float* coors = (const float*)d_in[1];
    const float* We1   = (const float*)d_in[2];
    const float* be1   = (const float*)d_in[3];
    const float* We2   = (const float*)d_in[4];
    const float* be2   = (const float*)d_in[5];
    const float* Wc1   = (const float*)d_in[6];
    const float* bc1   = (const float*)d_in[7];
    const float* Wc2   = (const float*)d_in[8];
    const float* bc2   = (const float*)d_in[9];
    const float* Wn1   = (const float*)d_in[10];
    const float* bn1   = (const float*)d_in[11];
    const float* Wn2   = (const float*)d_in[12];
    const float* bn2   = (const float*)d_in[13];
    float* out = (float*)d_out;
    float* node_out  = out;
    float* coors_out = out + NODE_OUT_ELEMS;

    float *pA, *pB, *pXC, *pH1;
    cudaGetSymbolAddress((void**)&pA, g_A);
    cudaGetSymbolAddress((void**)&pB, g_B);
    cudaGetSymbolAddress((void**)&pXC, g_XC);
    cudaGetSymbolAddress((void**)&pH1, g_H1);

    cudaFuncSetAttribute(edge_kernel, cudaFuncAttributeMaxDynamicSharedMemorySize, EK_SMEM_BYTES);

    // 1) KNN
    knn_kernel<<<NODES / 8, 256>>>(coors);

    // 2) A = feats @ We1[0:128,:] + be1 ; B = feats @ We1[128:256,:]  (pad->544)
    gemm_kernel<<<dim3(9, NODES / 64), 256>>>(feats, DIMF, We1, HID, be1, nullptr, 0,
                                              pA, EPAD, HID, EPAD, DIMF, 0);
    gemm_kernel<<<dim3(9, NODES / 64), 256>>>(feats, DIMF, We1 + 128 * HID, HID, nullptr, nullptr, 0,
                                              pB, EPAD, HID, EPAD, DIMF, 0);

    // 3) edges: m_ij -> m_i (XC[:,128:144]), coors_out
    edge_kernel<<<NODES / NODES_PER_BLK, 512, EK_SMEM_BYTES>>>(coors, We1, We2, be2,
                                                               Wc1, bc1, Wc2, bc2, coors_out);

    // 4) XC[:, 0:128] = feats
    copy_feats_kernel<<<(NODES * DIMF) / 256, 256>>>(feats);

    // 5) node MLP
    gemm_kernel<<<dim3(4, NODES / 64), 256>>>(pXC, 144, Wn1, 256, bn1, nullptr, 0,
                                              pH1, 256, 256, 256, 144, 1);
    gemm_kernel<<<dim3(2, NODES / 64), 256>>>(pH1, 256, Wn2, DIMF, bn2, feats, DIMF,
                                              node_out, DIMF, DIMF, DIMF, 256, 0);
}

// round 7
// speedup vs baseline: 1.2070x; 1.2070x over previous
#include <cuda_runtime.h>
#include <cuda_bf16.h>
#include <math.h>
#include <stdint.h>

#define BB 2
#define NNODES 4096
#define DIMF 128
#define KNN 32
#define HID 530
#define EPAD 544                    // padded hidden (17*32)
#define NODES (BB*NNODES)           // 8192
#define NODE_OUT_ELEMS (NODES*DIMF)

typedef unsigned long long ull;

// ---------------- scratch (static device arrays; no allocation) -------------
__device__ float g_A[NODES * EPAD];    // feats@We1[0:128]+be1 (pad cols zero)
__device__ float g_B[NODES * EPAD];    // feats@We1[128:256]   (pad cols zero)
__device__ float g_XC[NODES * 144];    // [feats | m_i]
__device__ float g_H1[NODES * 256];    // node hidden
__device__ int   g_knn[NODES * KNN];

// ---------------- f32x2 helpers ---------------------------------------------
__device__ __forceinline__ ull pack2(float lo, float hi) {
    ull u; asm("mov.b64 %0, {%1, %2};" : "=l"(u) : "f"(lo), "f"(hi)); return u;
}
__device__ __forceinline__ float2 unpack2(ull u) {
    float2 v; asm("mov.b64 {%0, %1}, %2;" : "=f"(v.x), "=f"(v.y) : "l"(u)); return v;
}
__device__ __forceinline__ void ffma2(ull& d, ull a, ull b) {
    asm("fma.rn.f32x2 %0, %1, %2, %0;" : "+l"(d) : "l"(a), "l"(b));
}
__device__ __forceinline__ ull fadd2(ull a, ull b) {
    ull d; asm("add.rn.f32x2 %0, %1, %2;" : "=l"(d) : "l"(a), "l"(b)); return d;
}

__device__ __forceinline__ float silu_f(float x) {
    float e = __expf(-x);
    return __fdividef(x, 1.0f + e);
}

__device__ __forceinline__ float dist2_f(float dx, float dy, float dz) {
    return __fadd_rn(__fadd_rn(__fmul_rn(dx, dx), __fmul_rn(dy, dy)), __fmul_rn(dz, dz));
}

// ---------------------------------------------------------------------------
// KNN: one warp per (b,i). Unsorted top-32 set via warp REDUX threshold.
// ---------------------------------------------------------------------------
__global__ __launch_bounds__(256) void knn_kernel(const float* __restrict__ coors) {
    const unsigned FULL = 0xffffffffu;
    int w    = blockIdx.x * 8 + (threadIdx.x >> 5);
    int lane = threadIdx.x & 31;
    int b = w >> 12;
    int i = w & (NNODES - 1);
    const float* cb = coors + (size_t)b * NNODES * 3;
    float qx = cb[3 * i + 0], qy = cb[3 * i + 1], qz = cb[3 * i + 2];

    float dx = qx - cb[3 * lane + 0];
    float dy = qy - cb[3 * lane + 1];
    float dz = qz - cb[3 * lane + 2];
    unsigned bu = __float_as_uint(dist2_f(dx, dy, dz));
    int bj = lane;
    unsigned curmax = __reduce_max_sync(FULL, bu);

    for (int j0 = 32; j0 < NNODES; j0 += 32) {
        int j = j0 + lane;
        float ex = qx - cb[3 * j + 0];
        float ey = qy - cb[3 * j + 1];
        float ez = qz - cb[3 * j + 2];
        unsigned du = __float_as_uint(dist2_f(ex, ey, ez));
        unsigned mask = __ballot_sync(FULL, du < curmax);
        while (mask) {
            int src = __ffs(mask) - 1;
            mask &= mask - 1;
            unsigned dc = __shfl_sync(FULL, du, src);
            if (dc < curmax) {
                unsigned mm = __ballot_sync(FULL, bu == curmax);
                int ml = __ffs(mm) - 1;
                if (lane == ml) { bu = dc; bj = j0 + src; }
                curmax = __reduce_max_sync(FULL, bu);
            }
        }
    }
    g_knn[(size_t)w * KNN + lane] = bj;
}

// ---------------------------------------------------------------------------
// Tiled fp32 GEMM (FFMA2): C[.. x Npad] = act(X @ W + b) (+resid); pads -> 0
// ---------------------------------------------------------------------------
__global__ __launch_bounds__(256) void gemm_kernel(
    const float* __restrict__ X, int ldx,
    const float* __restrict__ W, int ldw,
    const float* __restrict__ bias,
    const float* __restrict__ resid, int ldr,
    float* __restrict__ C, int ldc,
    int Nw, int Npad, int K, int act)
{
    __shared__ float Xs[16][68];
    __shared__ float Ws[16][68];
    int tid = threadIdx.x;
    int tx = tid & 15, ty = tid >> 4;
    int m0 = blockIdx.y * 64, n0 = blockIdx.x * 64;

    int lm  = tid >> 2;
    int lk  = (tid & 3) * 4;
    int wn  = tid & 63;
    int wkb = (tid >> 6) * 4;

    ull acc2[4][2];
#pragma unroll
    for (int a = 0; a < 4; a++) { acc2[a][0] = 0ull; acc2[a][1] = 0ull; }

    for (int kt = 0; kt < K; kt += 16) {
        float4 xv = *reinterpret_cast<const float4*>(X + (size_t)(m0 + lm) * ldx + kt + lk);
        Xs[lk + 0][lm] = xv.x;
        Xs[lk + 1][lm] = xv.y;
        Xs[lk + 2][lm] = xv.z;
        Xs[lk + 3][lm] = xv.w;
#pragma unroll
        for (int q = 0; q < 4; q++) {
            int k = wkb + q;
            float v = (n0 + wn < Nw) ? W[(size_t)(kt + k) * ldw + n0 + wn] : 0.f;
            Ws[k][wn] = v;
        }
        __syncthreads();
#pragma unroll
        for (int k = 0; k < 16; k++) {
            float4 a4 = *reinterpret_cast<const float4*>(&Xs[k][ty * 4]);
            float4 b4 = *reinterpret_cast<const float4*>(&Ws[k][tx * 4]);
            ull b01 = pack2(b4.x, b4.y);
            ull b23 = pack2(b4.z, b4.w);
            float av[4] = {a4.x, a4.y, a4.z, a4.w};
#pragma unroll
            for (int mi = 0; mi < 4; mi++) {
                ull aa = pack2(av[mi], av[mi]);
                ffma2(acc2[mi][0], aa, b01);
                ffma2(acc2[mi][1], aa, b23);
            }
        }
        __syncthreads();
    }

#pragma unroll
    for (int mi = 0; mi < 4; mi++) {
        int m = m0 + ty * 4 + mi;
        float2 lo = unpack2(acc2[mi][0]);
        float2 hi = unpack2(acc2[mi][1]);
        float accv[4] = {lo.x, lo.y, hi.x, hi.y};
#pragma unroll
        for (int ni = 0; ni < 4; ni++) {
            int n = n0 + tx * 4 + ni;
            if (n < Npad) {
                float v = accv[ni];
                if (n < Nw) {
                    if (bias) v += bias[n];
                    if (act) v = silu_f(v);
                    if (resid) v += resid[(size_t)m * ldr + n];
                } else {
                    v = 0.f;
                }
                C[(size_t)m * ldc + n] = v;
            }
        }
    }
}

// ---------------------------------------------------------------------------
__global__ __launch_bounds__(256) void copy_feats_kernel(const float* __restrict__ feats) {
    int idx = blockIdx.x * 256 + threadIdx.x;  // over NODES*128
    int n = idx >> 7, c = idx & 127;
    g_XC[(size_t)n * 144 + c] = feats[idx];
}

// ---------------------------------------------------------------------------
// Edge kernel: 256 threads (8 warps), 4 nodes/block, 3 blocks/SM target.
// Per node: 2 half-passes of 16 edges (warp -> 2 edges). A row staged in smem.
// Conflict-free packed weights, FFMA2 math, fully-unrolled loop with
// register-resident depth-4 B prefetch.
// ---------------------------------------------------------------------------
// byte offsets in dynamic smem:
#define OFF_WE2P 0                               // ulonglong2[4*544] = 34816
#define OFF_FTA  34816                           // ulonglong2[2*544] = 17408
#define OFF_FTB  52224                           // ull[544] = 4352
#define OFF_F2   56576                           // ull[32*6] = 1536
#define OFF_AS   58112                           // float[544] = 2176
#define OFF_FLT  60288
#define FI_WC1 0
#define FI_BC1 1024
#define FI_WC2 1088
#define FI_BE2 1152
#define FI_RC  1168
#define FI_MS  1296
#define FI_CW  1808
#define FI_EBO 1840
#define FI_TOT 1872
#define EK_SMEM_BYTES (OFF_FLT + FI_TOT*4)       // 67776

__global__ __launch_bounds__(256, 3) void edge_kernel(
    const float* __restrict__ coors,
    const float* __restrict__ We1,
    const float* __restrict__ We2,
    const float* __restrict__ be2,
    const float* __restrict__ Wc1,
    const float* __restrict__ bc1,
    const float* __restrict__ Wc2,
    const float* __restrict__ bc2,
    float* __restrict__ coors_out)
{
    extern __shared__ char smc[];
    ulonglong2* We2P = (ulonglong2*)(smc + OFF_WE2P);
    ulonglong2* FTA  = (ulonglong2*)(smc + OFF_FTA);
    ull* FTB = (ull*)(smc + OFF_FTB);
    ull* F2u = (ull*)(smc + OFF_F2);
    float* As  = (float*)(smc + OFF_AS);
    float* smf  = (float*)(smc + OFF_FLT);
    float* Wc1s = smf + FI_WC1;
    float* bc1s = smf + FI_BC1;
    float* Wc2s = smf + FI_WC2;
    float* be2s = smf + FI_BE2;
    float* rc_s = smf + FI_RC;                    // [32][4]
    float* ms   = smf + FI_MS;                    // [32][16]
    float* cw_s = smf + FI_CW;                    // [32]
    uint32_t* ebo_s = (uint32_t*)(smf + FI_EBO);  // [32]

    int tid = threadIdx.x;
    int w = tid >> 5, lane = tid & 31;
    const unsigned FULL = 0xffffffffu;
    float bc2v = bc2[0];

    // ---- weight preamble (once per block) ----
    for (int idx = tid; idx < 4 * EPAD; idx += 256) {
        int p = idx / EPAD, c = idx - p * EPAD;
        ulonglong2 v; v.x = 0ull; v.y = 0ull;
        if (c < HID) {
            v.x = pack2(We2[c * 16 + 4 * p + 0], We2[c * 16 + 4 * p + 1]);
            v.y = pack2(We2[c * 16 + 4 * p + 2], We2[c * 16 + 4 * p + 3]);
        }
        We2P[idx] = v;
    }
    for (int idx = tid; idx < 2 * EPAD; idx += 256) {
        int t = idx / EPAD, c = idx - t * EPAD;
        ulonglong2 v; v.x = 0ull; v.y = 0ull;
        if (c < HID) {
            v.x = pack2(We1[(size_t)(256 + 4 * t + 0) * HID + c], We1[(size_t)(256 + 4 * t + 1) * HID + c]);
            v.y = pack2(We1[(size_t)(256 + 4 * t + 2) * HID + c], We1[(size_t)(256 + 4 * t + 3) * HID + c]);
        }
        FTA[idx] = v;
    }
    for (int c = tid; c < EPAD; c += 256) {
        ull v = 0ull;
        if (c < HID) v = pack2(We1[(size_t)264 * HID + c], 0.f);
        FTB[c] = v;
    }
    for (int idx = tid; idx < 16 * 64; idx += 256) Wc1s[idx] = Wc1[idx];
    if (tid < 64) { bc1s[tid] = bc1[tid]; Wc2s[tid] = Wc2[tid]; }
    if (tid >= 64 && tid < 80) be2s[tid - 64] = be2[tid - 64];

#pragma unroll 1
    for (int nn = 0; nn < 4; nn++) {
        int node = blockIdx.x * 4 + nn;
        int b = node >> 12, i = node & (NNODES - 1);
        const float* cb = coors + (size_t)b * NNODES * 3;
        const float* Ap = g_A + (size_t)node * EPAD;

        // ---- stage A row + per-edge setup ----
        for (int idx = tid; idx < EPAD; idx += 256) As[idx] = Ap[idx];
        if (tid < 32) {
            int e = tid;
            int j = g_knn[(size_t)node * KNN + e];
            ebo_s[e] = (uint32_t)(b * NNODES + j);
            float dx = cb[3 * i + 0] - cb[3 * j + 0];
            float dy = cb[3 * i + 1] - cb[3 * j + 1];
            float dz = cb[3 * i + 2] - cb[3 * j + 2];
            float d = dist2_f(dx, dy, dz);
            rc_s[e * 4 + 0] = dx; rc_s[e * 4 + 1] = dy; rc_s[e * 4 + 2] = dz; rc_s[e * 4 + 3] = 0.f;
            float s0, c0, s1, c1, s2, c2, s3, c3;
            sincosf(d,          &s0, &c0);
            sincosf(d * 0.5f,   &s1, &c1);
            sincosf(d * 0.25f,  &s2, &c2);
            sincosf(d * 0.125f, &s3, &c3);
            F2u[e * 6 + 0] = pack2(s0, s1);
            F2u[e * 6 + 1] = pack2(s2, s3);
            F2u[e * 6 + 2] = pack2(c0, c1);
            F2u[e * 6 + 3] = pack2(c2, c3);
            F2u[e * 6 + 4] = pack2(d, 0.f);
        }
        __syncthreads();

        // ---- mainloop: two half-passes of 16 edges ----
#pragma unroll 1
        for (int hp = 0; hp < 2; hp++) {
            int e0 = hp * 16 + w * 2;
            ull fp0[5], fp1[5];
#pragma unroll
            for (int t = 0; t < 5; t++) { fp0[t] = F2u[(e0 + 0) * 6 + t]; fp1[t] = F2u[(e0 + 1) * 6 + t]; }

            const float* Bp0 = g_B + (size_t)ebo_s[e0 + 0] * EPAD;
            const float* Bp1 = g_B + (size_t)ebo_s[e0 + 1] * EPAD;

            ull m[16];
#pragma unroll
            for (int q = 0; q < 16; q++) m[q] = 0ull;

            // depth-4 register prefetch of B (indices constant under full unroll)
            float pb0[4], pb1[4];
#pragma unroll
            for (int p = 0; p < 4; p++) {
                pb0[p] = Bp0[p * 32 + lane];
                pb1[p] = Bp1[p * 32 + lane];
            }

#pragma unroll
            for (int it = 0; it < 17; it++) {
                int c = it * 32 + lane;
                float bv0 = pb0[it & 3], bv1 = pb1[it & 3];
                if (it + 4 < 17) {
                    pb0[it & 3] = Bp0[c + 128];
                    pb1[it & 3] = Bp1[c + 128];
                }
                float av = As[c];

                ulonglong2 fta0 = FTA[c];
                ulonglong2 fta1 = FTA[EPAD + c];
                ull        ftb  = FTB[c];

                ull h0a = pack2(av + bv0, 0.f);
                ull h0b = 0ull;
                ffma2(h0a, fp0[0], fta0.x);
                ffma2(h0b, fp0[1], fta0.y);
                ffma2(h0a, fp0[2], fta1.x);
                ffma2(h0b, fp0[3], fta1.y);
                ffma2(h0a, fp0[4], ftb);
                float2 h0v = unpack2(fadd2(h0a, h0b));
                float sh0 = silu_f(h0v.x + h0v.y);

                ull h1a = pack2(av + bv1, 0.f);
                ull h1b = 0ull;
                ffma2(h1a, fp1[0], fta0.x);
                ffma2(h1b, fp1[1], fta0.y);
                ffma2(h1a, fp1[2], fta1.x);
                ffma2(h1b, fp1[3], fta1.y);
                ffma2(h1a, fp1[4], ftb);
                float2 h1v = unpack2(fadd2(h1a, h1b));
                float sh1 = silu_f(h1v.x + h1v.y);

                ull sh0p = pack2(sh0, sh0);
                ull sh1p = pack2(sh1, sh1);

                ulonglong2 w0 = We2P[0 * EPAD + c];
                ulonglong2 w1 = We2P[1 * EPAD + c];
                ulonglong2 w2 = We2P[2 * EPAD + c];
                ulonglong2 w3 = We2P[3 * EPAD + c];

                ffma2(m[0], sh0p, w0.x); ffma2(m[1], sh0p, w0.y);
                ffma2(m[2], sh0p, w1.x); ffma2(m[3], sh0p, w1.y);
                ffma2(m[4], sh0p, w2.x); ffma2(m[5], sh0p, w2.y);
                ffma2(m[6], sh0p, w3.x); ffma2(m[7], sh0p, w3.y);

                ffma2(m[8],  sh1p, w0.x); ffma2(m[9],  sh1p, w0.y);
                ffma2(m[10], sh1p, w1.x); ffma2(m[11], sh1p, w1.y);
                ffma2(m[12], sh1p, w2.x); ffma2(m[13], sh1p, w2.y);
                ffma2(m[14], sh1p, w3.x); ffma2(m[15], sh1p, w3.y);
            }

            // ---- reduce-scatter: final k = lane&15, q = lane>>4 ----
            bool up;
            up = (lane & 16);
#pragma unroll
            for (int v = 0; v < 8; v++) {
                ull give = up ? m[v] : m[v + 8];
                ull recv = __shfl_xor_sync(FULL, give, 16);
                ull keep = up ? m[v + 8] : m[v];
                m[v] = fadd2(keep, recv);
            }
            up = (lane & 8);
#pragma unroll
            for (int v = 0; v < 4; v++) {
                ull give = up ? m[v] : m[v + 4];
                ull recv = __shfl_xor_sync(FULL, give, 8);
                ull keep = up ? m[v + 4] : m[v];
                m[v] = fadd2(keep, recv);
            }
            up = (lane & 4);
#pragma unroll
            for (int v = 0; v < 2; v++) {
                ull give = up ? m[v] : m[v + 2];
                ull recv = __shfl_xor_sync(FULL, give, 4);
                ull keep = up ? m[v + 2] : m[v];
                m[v] = fadd2(keep, recv);
            }
            up = (lane & 2);
            {
                ull give = up ? m[0] : m[1];
                ull recv = __shfl_xor_sync(FULL, give, 2);
                ull keep = up ? m[1] : m[0];
                m[0] = fadd2(keep, recv);
            }
            float2 v2 = unpack2(m[0]);
            bool upc = (lane & 1);
            float give = upc ? v2.x : v2.y;
            float recv = __shfl_xor_sync(FULL, give, 1);
            float tot = (upc ? v2.y : v2.x) + recv;
            int k = lane & 15, q = lane >> 4;
            ms[(e0 + q) * 16 + k] = silu_f(tot + be2s[k]);
        }
        __syncthreads();

        // ---- coors MLP: 8 threads per edge ----
        {
            int e = tid >> 3, li = tid & 7;
            float wpart = 0.f;
#pragma unroll
            for (int q = 0; q < 8; q++) {
                int l = li * 8 + q;
                float u = bc1s[l];
#pragma unroll
                for (int k = 0; k < 16; k++)
                    u = fmaf(ms[e * 16 + k], Wc1s[k * 64 + l], u);
                wpart = fmaf(silu_f(u), Wc2s[l], wpart);
            }
            wpart += __shfl_xor_sync(FULL, wpart, 1);
            wpart += __shfl_xor_sync(FULL, wpart, 2);
            wpart += __shfl_xor_sync(FULL, wpart, 4);
            if (li == 0) cw_s[e] = wpart + bc2v;
        }
        __syncthreads();

        // ---- m_i (threads 0-15) and coors_out (warp 1) ----
        if (tid < 16) {
            float s = 0.f;
#pragma unroll 8
            for (int e2 = 0; e2 < 32; e2++) s += ms[e2 * 16 + tid];
            g_XC[(size_t)node * 144 + 128 + tid] = s;
        }
        if (w == 1) {
            int e2 = lane;
            float wv = cw_s[e2];
            float px = wv * rc_s[e2 * 4 + 0];
            float py = wv * rc_s[e2 * 4 + 1];
            float pz = wv * rc_s[e2 * 4 + 2];
#pragma unroll
            for (int off = 16; off > 0; off >>= 1) {
                px += __shfl_down_sync(FULL, px, off);
                py += __shfl_down_sync(FULL, py, off);
                pz += __shfl_down_sync(FULL, pz, off);
            }
            if (lane == 0) {
                float* co = coors_out + (size_t)node * 3;
                co[0] = cb[3 * i + 0] + px;
                co[1] = cb[3 * i + 1] + py;
                co[2] = cb[3 * i + 2] + pz;
            }
        }
        __syncthreads();
    }
}

// ---------------------------------------------------------------------------
extern "C" void kernel_launch(void* const* d_in, const int* in_sizes, int n_in,
                              void* d_out, int out_size) {
    const float* feats = (const float*)d_in[0];
    const float* coors = (const float*)d_in[1];
    const float* We1   = (const float*)d_in[2];
    const float* be1   = (const float*)d_in[3];
    const float* We2   = (const float*)d_in[4];
    const float* be2   = (const float*)d_in[5];
    const float* Wc1   = (const float*)d_in[6];
    const float* bc1   = (const float*)d_in[7];
    const float* Wc2   = (const float*)d_in[8];
    const float* bc2   = (const float*)d_in[9];
    const float* Wn1   = (const float*)d_in[10];
    const float* bn1   = (const float*)d_in[11];
    const float* Wn2   = (const float*)d_in[12];
    const float* bn2   = (const float*)d_in[13];
    float* out = (float*)d_out;
    float* node_out  = out;
    float* coors_out = out + NODE_OUT_ELEMS;

    float *pA, *pB, *pXC, *pH1;
    cudaGetSymbolAddress((void**)&pA, g_A);
    cudaGetSymbolAddress((void**)&pB, g_B);
    cudaGetSymbolAddress((void**)&pXC, g_XC);
    cudaGetSymbolAddress((void**)&pH1, g_H1);

    cudaFuncSetAttribute(edge_kernel, cudaFuncAttributeMaxDynamicSharedMemorySize, EK_SMEM_BYTES);

    // 1) KNN
    knn_kernel<<<NODES / 8, 256>>>(coors);

    // 2) A = feats @ We1[0:128,:] + be1 ; B = feats @ We1[128:256,:]  (pad->544)
    gemm_kernel<<<dim3(9, NODES / 64), 256>>>(feats, DIMF, We1, HID, be1, nullptr, 0,
                                              pA, EPAD, HID, EPAD, DIMF, 0);
    gemm_kernel<<<dim3(9, NODES / 64), 256>>>(feats, DIMF, We1 + 128 * HID, HID, nullptr, nullptr, 0,
                                              pB, EPAD, HID, EPAD, DIMF, 0);

    // 3) edges: m_ij -> m_i (XC[:,128:144]), coors_out
    edge_kernel<<<NODES / 4, 256, EK_SMEM_BYTES>>>(coors, We1, We2, be2,
                                                   Wc1, bc1, Wc2, bc2, coors_out);

    // 4) XC[:, 0:128] = feats
    copy_feats_kernel<<<(NODES * DIMF) / 256, 256>>>(feats);

    // 5) node MLP
    gemm_kernel<<<dim3(4, NODES / 64), 256>>>(pXC, 144, Wn1, 256, bn1, nullptr, 0,
                                              pH1, 256, 256, 256, 144, 1);
    gemm_kernel<<<dim3(2, NODES / 64), 256>>>(pH1, 256, Wn2, DIMF, bn2, feats, DIMF,
                                              node_out, DIMF, DIMF, DIMF, 256, 0);
}